// round 1
// baseline (speedup 1.0000x reference)
#include <cuda_runtime.h>
#include <cstdint>

#define Bsz 128
#define Ssz 512
#define Hsz 1024
#define NL  4

// out layout: output [512,128,1024], state_h [4,128,1024], state_c [4,128,1024]
#define OUT_OFF_H ((size_t)512 * 128 * 1024)
#define OUT_OFF_C (OUT_OFF_H + (size_t)4 * 128 * 1024)

// ---------------- scratch (__device__ globals; no allocations allowed) ------
__device__ int   d_len[Bsz];
__device__ int   d_sorted[Bsz];
__device__ int   d_unsort[Bsz];
__device__ int   d_bslast;
__device__ float d_xt[2][Bsz][Hsz];          // ping-pong layer activations (sorted order)
__device__ float d_G[3][3][Bsz][Hsz];        // [kpart][gate(i,g,o)][r][hcol]

// ---------------- kernel 1: lengths[b] = count(x[b,:] > 0) ------------------
__global__ void k_lengths(const int* __restrict__ x) {
    int b = blockIdx.x;
    int t = threadIdx.x;
    int cnt = 0;
    for (int s = t; s < Ssz; s += blockDim.x) cnt += (x[b * Ssz + s] > 0);
    #pragma unroll
    for (int o = 16; o; o >>= 1) cnt += __shfl_down_sync(0xFFFFFFFFu, cnt, o);
    __shared__ int ws[8];
    if ((t & 31) == 0) ws[t >> 5] = cnt;
    __syncthreads();
    if (t == 0) {
        int s = 0;
        for (int w = 0; w < (int)blockDim.x / 32; w++) s += ws[w];
        d_len[b] = s;
    }
}

// ---------------- kernel 2: stable descending argsort (B=128, O(B^2)) -------
__global__ void k_sort() {
    __shared__ int sl[Bsz];
    int i = threadIdx.x;
    sl[i] = d_len[i];
    __syncthreads();
    int li = sl[i];
    int rank = 0, c512 = 0;
    #pragma unroll 8
    for (int j = 0; j < Bsz; j++) {
        int lj = sl[j];
        rank += (lj > li) || (lj == li && j < i);
        c512 += (lj >= Ssz);
    }
    d_unsort[i] = rank;
    d_sorted[rank] = i;
    if (i == 0) d_bslast = c512;
}

// ---------------- kernel 3: xt0[r,:] = emb[ x[sorted[r], 0] ] ---------------
__global__ void k_gather(const int* __restrict__ x, const float* __restrict__ emb) {
    int r = blockIdx.x;
    int tok = x[d_sorted[r] * Ssz];  // t = 0
    const float4* src = (const float4*)(emb + (size_t)tok * Hsz);
    float4* dst = (float4*)&d_xt[0][r][0];
    dst[threadIdx.x] = src[threadIdx.x];
}

// ---------------- kernel 4: GEMM  G[gate][r][hcol] = xt @ W_sel^T -----------
// Only gates i (rows 0..1023), g (2048..3071), o (3072..4095) of W_ih are used.
// C tile: BN=32 (gate cols) x BM=128 (all rows), split-K = 3, BK = 16.
#define BN 32
#define BK 16
__global__ void __launch_bounds__(256) k_gemm(const float* __restrict__ W, int cur) {
    __shared__ __align__(16) float As[BK][36];    // [k][n], padded
    __shared__ __align__(16) float Bs[BK][132];   // [k][m], padded

    int n0    = blockIdx.x * BN;
    int gate  = n0 >> 10;                 // 0,1,2 -> i,g,o
    int hbase = n0 & 1023;
    int wbase = ((gate + (gate > 0)) << 10) + hbase;  // 0->0, 1->2048, 2->3072 base
    const float* A  = W + (size_t)wbase * Hsz;
    const float* Bx = &d_xt[cur][0][0];

    int part = blockIdx.y;                 // split-K part
    int s0 = (part * 64) / 3;              // 64 k-steps of 16 total
    int s1 = ((part + 1) * 64) / 3;

    int tid = threadIdx.x;
    int tx = tid & 31;       // m-group: rows tx*4 .. tx*4+3
    int ty = tid >> 5;       // n-group: cols ty*4 .. ty*4+3
    float acc[4][4] = {};

    for (int st = s0; st < s1; st++) {
        int kk = st * BK;
        #pragma unroll
        for (int e = 0; e < 2; e++) {      // A: 32x16
            int f = tid + e * 256;
            int n = f >> 4, k = f & 15;
            As[k][n] = A[(size_t)n * Hsz + kk + k];
        }
        #pragma unroll
        for (int e = 0; e < 8; e++) {      // B: 128x16
            int f = tid + e * 256;
            int m = f >> 4, k = f & 15;
            Bs[k][m] = Bx[(size_t)m * Hsz + kk + k];
        }
        __syncthreads();
        #pragma unroll
        for (int k = 0; k < BK; k++) {
            float4 a4 = *(const float4*)&As[k][ty * 4];
            float4 b4 = *(const float4*)&Bs[k][tx * 4];
            float av[4] = {a4.x, a4.y, a4.z, a4.w};
            float bv[4] = {b4.x, b4.y, b4.z, b4.w};
            #pragma unroll
            for (int i = 0; i < 4; i++)
                #pragma unroll
                for (int j = 0; j < 4; j++)
                    acc[i][j] += av[i] * bv[j];
        }
        __syncthreads();
    }

    float* Gp = &d_G[part][gate][0][0];
    #pragma unroll
    for (int j = 0; j < 4; j++) {
        int r = tx * 4 + j;
        float4 v = make_float4(acc[0][j], acc[1][j], acc[2][j], acc[3][j]);
        *(float4*)&Gp[(size_t)r * Hsz + hbase + ty * 4] = v;
    }
}

// ---------------- kernel 5: activation epilogue per layer -------------------
__device__ __forceinline__ float sigmoidf_(float x) { return 1.0f / (1.0f + expf(-x)); }

__global__ void k_act(const float* __restrict__ bih, const float* __restrict__ bhh,
                      int l, int cur, float* __restrict__ out) {
    int r = blockIdx.x;
    int h0 = threadIdx.x * 4;
    float m = (r < d_bslast) ? 1.0f : 0.0f;
    #pragma unroll
    for (int c = 0; c < 4; c++) {
        int hc = h0 + c;
        float gi = d_G[0][0][r][hc] + d_G[1][0][r][hc] + d_G[2][0][r][hc]
                 + bih[hc] + bhh[hc];
        float gg = d_G[0][1][r][hc] + d_G[1][1][r][hc] + d_G[2][1][r][hc]
                 + bih[2 * Hsz + hc] + bhh[2 * Hsz + hc];
        float go = d_G[0][2][r][hc] + d_G[1][2][r][hc] + d_G[2][2][r][hc]
                 + bih[3 * Hsz + hc] + bhh[3 * Hsz + hc];
        float cc = sigmoidf_(gi) * tanhf(gg);
        float hh = sigmoidf_(go) * tanhf(cc);
        d_xt[cur ^ 1][r][hc] = hh;
        out[OUT_OFF_H + ((size_t)l * Bsz + r) * Hsz + hc] = hh * m;
        out[OUT_OFF_C + ((size_t)l * Bsz + r) * Hsz + hc] = cc * m;
    }
}

// ---------------- kernel 6: output[t,b,:] = (t < len[b]) * h_top[b,:] -------
__global__ void k_output(float* __restrict__ out, int finalbuf) {
    int b  = blockIdx.x;
    int tb = blockIdx.y * 64;
    int len = d_len[b];
    int rk  = d_unsort[b];
    float4 hv = *(const float4*)&d_xt[finalbuf][rk][threadIdx.x * 4];
    float4 z  = make_float4(0.f, 0.f, 0.f, 0.f);
    size_t col = (size_t)threadIdx.x * 4;
    #pragma unroll 4
    for (int t = tb; t < tb + 64; t++) {
        float4 v = (t < len) ? hv : z;
        *(float4*)&out[(((size_t)t * Bsz) + b) * Hsz + col] = v;
    }
}

// ---------------- launch -----------------------------------------------------
extern "C" void kernel_launch(void* const* d_in, const int* in_sizes, int n_in,
                              void* d_out, int out_size) {
    const int*   x    = (const int*)d_in[0];
    const float* emb  = (const float*)d_in[1];
    const float* W_ih = (const float*)d_in[2];
    // d_in[3] = W_hh: unused (h0 == 0)
    const float* b_ih = (const float*)d_in[4];
    const float* b_hh = (const float*)d_in[5];
    float* out = (float*)d_out;

    k_lengths<<<Bsz, 256>>>(x);
    k_sort<<<1, Bsz>>>();
    k_gather<<<Bsz, 256>>>(x, emb);
    for (int l = 0; l < NL; l++) {
        int cur = l & 1;
        k_gemm<<<dim3(96, 3), 256>>>(W_ih + (size_t)l * 4 * Hsz * Hsz, cur);
        k_act<<<Bsz, 256>>>(b_ih + (size_t)l * 4 * Hsz, b_hh + (size_t)l * 4 * Hsz, l, cur, out);
    }
    k_output<<<dim3(Bsz, 8), 256>>>(out, /*finalbuf=*/0);
}

// round 3
// speedup vs baseline: 1.0582x; 1.0582x over previous
#include <cuda_runtime.h>
#include <cstdint>

#define Bsz 128
#define Ssz 512
#define Hsz 1024
#define NL  4
#define NPART 6

// out layout: output [512,128,1024], state_h [4,128,1024], state_c [4,128,1024]
#define OUT_OFF_H ((size_t)512 * 128 * 1024)
#define OUT_OFF_C (OUT_OFF_H + (size_t)4 * 128 * 1024)

// ---------------- scratch (__device__ globals; no allocations allowed) ------
__device__ int   d_len[Bsz];
__device__ int   d_sorted[Bsz];
__device__ int   d_unsort[Bsz];
__device__ int   d_bslast;
__device__ float d_xtT[2][Hsz][Bsz];           // transposed activations [hc][r], sorted order
__device__ float d_hfin[Bsz][Hsz];             // final top-layer h, row-major [r][hc]
__device__ float d_G2[NPART][3 * Hsz][Bsz];    // split-K partials: [part][vm][r]

// ---------------- kernel 1: lengths[b] = count(x[b,:] > 0) ------------------
__global__ void k_lengths(const int* __restrict__ x) {
    int b = blockIdx.x;
    int t = threadIdx.x;
    int cnt = 0;
    for (int s = t; s < Ssz; s += blockDim.x) cnt += (x[b * Ssz + s] > 0);
    #pragma unroll
    for (int o = 16; o; o >>= 1) cnt += __shfl_down_sync(0xFFFFFFFFu, cnt, o);
    __shared__ int ws[8];
    if ((t & 31) == 0) ws[t >> 5] = cnt;
    __syncthreads();
    if (t == 0) {
        int s = 0;
        for (int w = 0; w < (int)blockDim.x / 32; w++) s += ws[w];
        d_len[b] = s;
    }
}

// ---------------- kernel 2: stable descending argsort (B=128, O(B^2)) -------
__global__ void k_sort() {
    __shared__ int sl[Bsz];
    int i = threadIdx.x;
    sl[i] = d_len[i];
    __syncthreads();
    int li = sl[i];
    int rank = 0, c512 = 0;
    #pragma unroll 8
    for (int j = 0; j < Bsz; j++) {
        int lj = sl[j];
        rank += (lj > li) || (lj == li && j < i);
        c512 += (lj >= Ssz);
    }
    d_unsort[i] = rank;
    d_sorted[rank] = i;
    if (i == 0) d_bslast = c512;
}

// ---------------- kernel 3: xt0T[hc][r] = emb[ x[sorted[r], 0] ][hc] --------
__global__ void k_gather(const int* __restrict__ x, const float* __restrict__ emb) {
    int r = blockIdx.x;
    int tok = x[d_sorted[r] * Ssz];  // t = 0
    #pragma unroll
    for (int j = 0; j < 4; j++) {
        int hc = threadIdx.x + j * 256;
        d_xtT[0][hc][r] = emb[(size_t)tok * Hsz + hc];
    }
}

// ---------------- kernel 4: 3xTF32 tensor-core GEMM -------------------------
// C[vm=3072 gate cols][r=128] = W_sel[vm][k] * xT[k][r], k = 1024, split-K 6.
// vm -> W row: vm<1024 -> vm (i), 1024..2047 -> vm+1024 (g), 2048..3071 -> vm+1024 (o)
#define AS_STRIDE 20    // 128 x 16 fp32 weight tile, pad to 20
#define BS_STRIDE 132   // 16 x 128 fp32 x tile [k][r], pad to 132

__device__ __forceinline__ unsigned f2tf(float f) {
    unsigned r; asm("cvt.rna.tf32.f32 %0, %1;" : "=r"(r) : "f"(f)); return r;
}
__device__ __forceinline__ void mma8(float* c, const unsigned* a, const unsigned* b) {
    asm volatile(
        "mma.sync.aligned.m16n8k8.row.col.f32.tf32.tf32.f32 "
        "{%0,%1,%2,%3}, {%4,%5,%6,%7}, {%8,%9}, {%0,%1,%2,%3};"
        : "+f"(c[0]), "+f"(c[1]), "+f"(c[2]), "+f"(c[3])
        : "r"(a[0]), "r"(a[1]), "r"(a[2]), "r"(a[3]), "r"(b[0]), "r"(b[1]));
}
__device__ __forceinline__ void cpa16(unsigned s, const float* g) {
    asm volatile("cp.async.cg.shared.global [%0], [%1], 16;" :: "r"(s), "l"(g));
}

__global__ void __launch_bounds__(256) k_gemm2(const float* __restrict__ W, int cur) {
    __shared__ __align__(16) float As[2][128 * AS_STRIDE];
    __shared__ __align__(16) float Bs[2][16 * BS_STRIDE];

    int tid  = threadIdx.x;
    int vm0  = blockIdx.x * 128;               // 0..2944
    int gate = vm0 >> 10;
    const float* A  = W + (size_t)(vm0 + (gate > 0 ? 1024 : 0)) * Hsz;
    const float* BT = &d_xtT[cur][0][0];

    int part = blockIdx.y;
    int i0 = part * 64 / NPART, i1 = (part + 1) * 64 / NPART;  // BK=16 stages
    int niter = i1 - i0;

    unsigned asb[2], bsb[2];
    asb[0] = (unsigned)__cvta_generic_to_shared(&As[0][0]);
    asb[1] = (unsigned)__cvta_generic_to_shared(&As[1][0]);
    bsb[0] = (unsigned)__cvta_generic_to_shared(&Bs[0][0]);
    bsb[1] = (unsigned)__cvta_generic_to_shared(&Bs[1][0]);

    // stage loader: A 128x16 (512 16B chunks) + B 16x128 (512 16B chunks) = 1024
    auto load_stage = [&](int buf, int iter) {
        int kw = iter * 16;
        #pragma unroll
        for (int e = 0; e < 4; e++) {
            int c = tid + e * 256;
            if (c < 512) {
                int row = c >> 2, seg = c & 3;            // A: 4 chunks/row of 16
                cpa16(asb[buf] + (unsigned)(row * AS_STRIDE + seg * 4) * 4,
                      A + (size_t)row * Hsz + kw + seg * 4);
            } else {
                int cb = c - 512;
                int kr = cb >> 5, seg = cb & 31;          // B: 32 chunks/row of 128
                cpa16(bsb[buf] + (unsigned)(kr * BS_STRIDE + seg * 4) * 4,
                      BT + (size_t)(kw + kr) * Bsz + seg * 4);
            }
        }
    };

    int lane = tid & 31, wid = tid >> 5;
    int wm = (wid & 3) * 32;      // warp m offset (gate cols)
    int wn = (wid >> 2) * 64;     // warp n offset (batch rows)
    int g  = lane >> 2, tg = lane & 3;

    float acc[2][8][4];
    #pragma unroll
    for (int a = 0; a < 2; a++)
        #pragma unroll
        for (int b = 0; b < 8; b++)
            #pragma unroll
            for (int cxx = 0; cxx < 4; cxx++) acc[a][b][cxx] = 0.f;

    load_stage(0, i0);
    asm volatile("cp.async.commit_group;" ::: "memory");

    for (int it = 0; it < niter; ++it) {
        if (it + 1 < niter) load_stage((it + 1) & 1, i0 + it + 1);
        asm volatile("cp.async.commit_group;" ::: "memory");
        asm volatile("cp.async.wait_group 1;" ::: "memory");
        __syncthreads();

        const float* As_ = &As[it & 1][0];
        const float* Bs_ = &Bs[it & 1][0];

        #pragma unroll
        for (int ks = 0; ks < 2; ks++) {
            int kb = ks * 8;
            unsigned bh[8][2], bl[8][2];
            #pragma unroll
            for (int nf = 0; nf < 8; nf++) {
                int n = wn + nf * 8 + g;
                float b0 = Bs_[(kb + tg) * BS_STRIDE + n];
                float b1 = Bs_[(kb + tg + 4) * BS_STRIDE + n];
                bh[nf][0] = f2tf(b0);
                bl[nf][0] = f2tf(b0 - __uint_as_float(bh[nf][0]));
                bh[nf][1] = f2tf(b1);
                bl[nf][1] = f2tf(b1 - __uint_as_float(bh[nf][1]));
            }
            #pragma unroll
            for (int mf = 0; mf < 2; mf++) {
                int row = wm + mf * 16 + g;
                float a0 = As_[row * AS_STRIDE + kb + tg];
                float a1 = As_[(row + 8) * AS_STRIDE + kb + tg];
                float a2 = As_[row * AS_STRIDE + kb + tg + 4];
                float a3 = As_[(row + 8) * AS_STRIDE + kb + tg + 4];
                unsigned ah[4] = {f2tf(a0), f2tf(a1), f2tf(a2), f2tf(a3)};
                unsigned al[4] = {f2tf(a0 - __uint_as_float(ah[0])),
                                  f2tf(a1 - __uint_as_float(ah[1])),
                                  f2tf(a2 - __uint_as_float(ah[2])),
                                  f2tf(a3 - __uint_as_float(ah[3]))};
                #pragma unroll
                for (int nf = 0; nf < 8; nf++) {
                    mma8(acc[mf][nf], ah, bh[nf]);
                    mma8(acc[mf][nf], al, bh[nf]);
                    mma8(acc[mf][nf], ah, bl[nf]);
                }
            }
        }
        __syncthreads();
    }

    // epilogue: write split-K partials, [vm][r], float2 per fragment row
    float* Gp = &d_G2[part][0][0];
    #pragma unroll
    for (int mf = 0; mf < 2; mf++)
        #pragma unroll
        for (int nf = 0; nf < 8; nf++) {
            int m0 = vm0 + wm + mf * 16 + g;
            int n0 = wn + nf * 8 + tg * 2;
            float2 v01 = make_float2(acc[mf][nf][0], acc[mf][nf][1]);
            float2 v23 = make_float2(acc[mf][nf][2], acc[mf][nf][3]);
            *(float2*)(Gp + (size_t)m0 * Bsz + n0)       = v01;
            *(float2*)(Gp + (size_t)(m0 + 8) * Bsz + n0) = v23;
        }
}

// ---------------- kernel 5: split-K reduce + LSTM activations ---------------
__device__ __forceinline__ float sigmoidf_(float x) { return 1.0f / (1.0f + expf(-x)); }

__global__ void __launch_bounds__(256) k_act2(const float* __restrict__ bih,
                                              const float* __restrict__ bhh,
                                              int l, int nxt, float* __restrict__ out) {
    __shared__ float sh[16][129], sc[16][129];
    int tid = threadIdx.x;
    int hb = blockIdx.x * 16;       // grid = 64 blocks
    int bsl = d_bslast;

    #pragma unroll
    for (int w = 0; w < 8; w++) {
        int idx = w * 256 + tid;
        int hcl = idx >> 7, r = idx & 127;
        int hc = hb + hcl;
        float gi = 0.f, gg = 0.f, go = 0.f;
        #pragma unroll
        for (int p = 0; p < NPART; p++) {
            gi += d_G2[p][hc][r];
            gg += d_G2[p][Hsz + hc][r];
            go += d_G2[p][2 * Hsz + hc][r];
        }
        gi += bih[hc] + bhh[hc];
        gg += bih[2 * Hsz + hc] + bhh[2 * Hsz + hc];
        go += bih[3 * Hsz + hc] + bhh[3 * Hsz + hc];
        float cc = sigmoidf_(gi) * tanhf(gg);
        float hh = sigmoidf_(go) * tanhf(cc);
        d_xtT[nxt][hc][r] = hh;           // unmasked h feeds next layer
        sh[hcl][r] = hh;
        sc[hcl][r] = cc;
    }
    __syncthreads();
    #pragma unroll
    for (int w = 0; w < 8; w++) {
        int idx = w * 256 + tid;
        int r = idx >> 4, hcl = idx & 15;
        float m = (r < bsl) ? 1.f : 0.f;
        size_t o = ((size_t)(l * Bsz + r) << 10) + hb + hcl;
        float hh = sh[hcl][r];
        out[OUT_OFF_H + o] = hh * m;
        out[OUT_OFF_C + o] = sc[hcl][r] * m;
        d_hfin[r][hb + hcl] = hh;          // row-major final h (last layer wins)
    }
}

// ---------------- kernel 6: output[t,b,:] = (t < len[b]) * h_top[b,:] -------
__global__ void k_output(float* __restrict__ out) {
    int b  = blockIdx.x;
    int tb = blockIdx.y * 64;
    int len = d_len[b];
    int rk  = d_unsort[b];
    float4 hv = *(const float4*)&d_hfin[rk][threadIdx.x * 4];
    float4 z  = make_float4(0.f, 0.f, 0.f, 0.f);
    size_t col = (size_t)threadIdx.x * 4;
    #pragma unroll 4
    for (int t = tb; t < tb + 64; t++) {
        float4 v = (t < len) ? hv : z;
        *(float4*)&out[(((size_t)t * Bsz) + b) * Hsz + col] = v;
    }
}

// ---------------- launch -----------------------------------------------------
extern "C" void kernel_launch(void* const* d_in, const int* in_sizes, int n_in,
                              void* d_out, int out_size) {
    const int*   x    = (const int*)d_in[0];
    const float* emb  = (const float*)d_in[1];
    const float* W_ih = (const float*)d_in[2];
    // d_in[3] = W_hh: unused (h0 == 0)
    const float* b_ih = (const float*)d_in[4];
    const float* b_hh = (const float*)d_in[5];
    float* out = (float*)d_out;

    k_lengths<<<Bsz, 256>>>(x);
    k_sort<<<1, Bsz>>>();
    k_gather<<<Bsz, 256>>>(x, emb);
    for (int l = 0; l < NL; l++) {
        int cur = l & 1;
        k_gemm2<<<dim3(24, NPART), 256>>>(W_ih + (size_t)l * 4 * Hsz * Hsz, cur);
        k_act2<<<64, 256>>>(b_ih + (size_t)l * 4 * Hsz, b_hh + (size_t)l * 4 * Hsz,
                            l, cur ^ 1, out);
    }
    k_output<<<dim3(Bsz, 8), 256>>>(out);
}